// round 6
// baseline (speedup 1.0000x reference)
#include <cuda_runtime.h>

#define NMAX 16384
#define KNN  16
#define CDIM 64
#define NODES_PER_BLOCK 4

#define KNN_WARPS 16          // warps per block; 2 queries per warp -> 32 q/block
#define KNN_THREADS (KNN_WARPS * 32)
#define KNN_TILE 2048         // candidates per smem tile (32KB packed)

#define FULLMASK 0xffffffffu
#define FINF __int_as_float(0x7f800000)

// ---- scratch (no allocation allowed) ----
__device__ float4     g_pos4[NMAX];
__device__ ulonglong2 g_pairA[NMAX / 2];   // (x-pair, y-pair) per 2 candidates
__device__ ulonglong2 g_pairB[NMAX / 2];   // (z-pair, w-pair)
__device__ int    g_knn[NMAX * KNN];
__device__ float  g_B[NMAX * CDIM];   // x @ W1b
__device__ float  g_C[NMAX * CDIM];   // x @ (W1a - W1b) + b1

// ---- packed f32x2 helpers ----
__device__ __forceinline__ unsigned long long pk2(float a, float b) {
    unsigned long long r;
    asm("mov.b64 %0, {%1, %2};" : "=l"(r) : "f"(a), "f"(b));
    return r;
}
__device__ __forceinline__ void upk2(unsigned long long v, float& a, float& b) {
    asm("mov.b64 {%0, %1}, %2;" : "=f"(a), "=f"(b) : "l"(v));
}
__device__ __forceinline__ unsigned long long fma2(unsigned long long a,
                                                   unsigned long long b,
                                                   unsigned long long c) {
    unsigned long long r;
    asm("fma.rn.f32x2 %0, %1, %2, %3;" : "=l"(r) : "l"(a), "l"(b), "l"(c));
    return r;
}
__device__ __forceinline__ unsigned long long mul2(unsigned long long a,
                                                   unsigned long long b) {
    unsigned long long r;
    asm("mul.rn.f32x2 %0, %1, %2;" : "=l"(r) : "l"(a), "l"(b));
    return r;
}
__device__ __forceinline__ unsigned long long add2(unsigned long long a,
                                                   unsigned long long b) {
    unsigned long long r;
    asm("add.rn.f32x2 %0, %1, %2;" : "=l"(r) : "l"(a), "l"(b));
    return r;
}

// ============================================================
// Kernel 0: pack pos -> float4 (queries) + paired f32x2 tiles (candidates)
// thread = pair of points
// ============================================================
__global__ void pack_pos_kernel(const float* __restrict__ pos, int n) {
    int i = blockIdx.x * blockDim.x + threadIdx.x;
    if (i < n / 2) {
        int a = 2 * i, b = 2 * i + 1;
        float xa = pos[a * 3 + 0], ya = pos[a * 3 + 1], za = pos[a * 3 + 2];
        float xb = pos[b * 3 + 0], yb = pos[b * 3 + 1], zb = pos[b * 3 + 2];
        float wa = fmaf(xa, xa, fmaf(ya, ya, za * za));
        float wb = fmaf(xb, xb, fmaf(yb, yb, zb * zb));
        g_pos4[a] = make_float4(xa, ya, za, wa);
        g_pos4[b] = make_float4(xb, yb, zb, wb);
        g_pairA[i] = make_ulonglong2(pk2(xa, xb), pk2(ya, yb));
        g_pairB[i] = make_ulonglong2(pk2(za, zb), pk2(wa, wb));
    }
}

// ============================================================
// Kernel 1: brute-force KNN — 2 queries per warp (16 lanes each).
// Both subgroups read the SAME tile addresses (2-way smem broadcast,
// conflict-free) -> smem traffic per query halved vs warp-per-query.
// Top-16 is one rank per lane (cs = rank). The insert loop is fully
// warp-uniform and advances one event per subgroup per iteration.
// ============================================================
__global__ __launch_bounds__(KNN_THREADS, 4)
void knn_kernel(int n) {
    __shared__ ulonglong2 tileA[KNN_TILE / 2];  // (x-pair, y-pair)
    __shared__ ulonglong2 tileB[KNN_TILE / 2];  // (z-pair, w-pair)

    const int tid  = threadIdx.x;
    const int w    = tid >> 5;
    const int lane = tid & 31;
    const int qs   = lane >> 4;          // subgroup (query within warp)
    const int cs   = lane & 15;          // rank / candidate-pair slot
    const int q    = blockIdx.x * (KNN_WARPS * 2) + w * 2 + qs;

    const float4 qp = g_pos4[q];
    const unsigned long long qx2 = pk2(qp.x, qp.x);
    const unsigned long long qy2 = pk2(qp.y, qp.y);
    const unsigned long long qz2 = pk2(qp.z, qp.z);
    const unsigned long long qw2 = pk2(qp.w, qp.w);
    const unsigned long long M2  = pk2(-2.0f, -2.0f);

    float bd = FINF;      // rank cs of this subgroup's sorted top-16
    int   bj = 0;
    float worst = FINF;   // current 16th smallest (subgroup-uniform)

    for (int t0 = 0; t0 < n; t0 += KNN_TILE) {
        const int pbase = t0 / 2;
        for (int c = tid; c < KNN_TILE / 2; c += KNN_THREADS) {
            tileA[c] = g_pairA[pbase + c];   // straight LDG.128 -> STS.128
            tileB[c] = g_pairB[pbase + c];
        }
        __syncthreads();

#pragma unroll 4
        for (int it = 0; it < KNN_TILE / 2; it += 16) {
            ulonglong2 A = tileA[it + cs];   // 16 distinct addrs, 2-way bcast
            ulonglong2 B = tileB[it + cs];
            unsigned long long acc = mul2(qz2, B.x);
            acc = fma2(qy2, A.y, acc);
            acc = fma2(qx2, A.x, acc);
            unsigned long long dd = fma2(M2, acc, add2(qw2, B.y));
            float d0, d1;
            upk2(dd, d0, d1);
            int pj = t0 + 2 * (it + cs);     // candidates pj, pj+1

            unsigned mfull = __ballot_sync(FULLMASK, (d0 < worst) | (d1 < worst));
            unsigned m0 = mfull & 0xFFFFu;   // subgroup 0 events
            unsigned m1 = mfull >> 16;       // subgroup 1 events
            while (m0 | m1) {                // warp-uniform
                int s0 = __ffs(m0) - 1;
                int s1 = __ffs(m1) - 1;
                m0 &= m0 - 1;                // (0 & ~0) == 0: safe when empty
                m1 &= m1 - 1;
                bool has = qs ? (s1 >= 0) : (s0 >= 0);
                int  src = qs ? (s1 < 0 ? 16 : 16 + s1)
                              : (s0 < 0 ? 0  : s0);
                float e0 = __shfl_sync(FULLMASK, d0, src);
                float e1 = __shfl_sync(FULLMASK, d1, src);
                int   j0 = __shfl_sync(FULLMASK, pj, src);

                // insert candidate j0 (distance e0)
                {
                    bool act = has && (e0 < worst) && (j0 != q); // sub-uniform
                    float bp = __shfl_up_sync(FULLMASK, bd, 1);
                    int   ip = __shfl_up_sync(FULLMASK, bj, 1);
                    unsigned gm = __ballot_sync(FULLMASK, act && (bd > e0));
                    if (act) {
                        int pos = __ffs((gm >> (qs << 4)) & 0xFFFFu) - 1;
                        if (cs > pos)       { bd = bp; bj = ip; }
                        else if (cs == pos) { bd = e0; bj = j0; }
                    }
                    worst = __shfl_sync(FULLMASK, bd, (qs << 4) + 15);
                }
                // insert candidate j0+1 (distance e1)
                {
                    bool act = has && (e1 < worst) && (j0 + 1 != q);
                    float bp = __shfl_up_sync(FULLMASK, bd, 1);
                    int   ip = __shfl_up_sync(FULLMASK, bj, 1);
                    unsigned gm = __ballot_sync(FULLMASK, act && (bd > e1));
                    if (act) {
                        int pos = __ffs((gm >> (qs << 4)) & 0xFFFFu) - 1;
                        if (cs > pos)       { bd = bp; bj = ip; }
                        else if (cs == pos) { bd = e1; bj = j0 + 1; }
                    }
                    worst = __shfl_sync(FULLMASK, bd, (qs << 4) + 15);
                }
            }
        }
        __syncthreads();
    }

    g_knn[q * KNN + cs] = bj;   // each subgroup writes its query's 16 ranks
}

// ============================================================
// Kernel 2: B = x @ W1b ; C = x @ (W1a - W1b) + b1
// ============================================================
__global__ void feat_kernel(const float* __restrict__ x,
                            const float* __restrict__ W1,
                            const float* __restrict__ b1, int n) {
    int t = blockIdx.x * blockDim.x + threadIdx.x;
    int nn = t >> 6;
    int d  = t & 63;
    if (nn >= n) return;
    const float* xr = x + nn * CDIM;
    float a = 0.0f, b = 0.0f;
#pragma unroll 8
    for (int c = 0; c < CDIM; c++) {
        float xv = xr[c];                           // warp broadcast, L1-hot
        a = fmaf(xv, W1[c * CDIM + d], a);          // W1a
        b = fmaf(xv, W1[(CDIM + c) * CDIM + d], b); // W1b
    }
    g_B[t] = b;
    g_C[t] = a - b + b1[d];
}

// ============================================================
// Kernel 3: per-node: g[k] = relu(C_i + B_j) (one sync), then 16x64
// matvec via packed fma.rn.f32x2 with FOUR accumulator chains
// (dependency depth 16 -> 8) + running max.
// ============================================================
__global__ __launch_bounds__(64)
void edge_kernel(const float* __restrict__ W2,
                 const float* __restrict__ b2,
                 float* __restrict__ out, int n) {
    __shared__ __align__(16) float gs[KNN][CDIM];
    const int d = threadIdx.x;

    // pack W2 column d as 32 f32x2 pairs (W2[2e][d], W2[2e+1][d])
    unsigned long long w2p[CDIM / 2];
#pragma unroll
    for (int e2 = 0; e2 < CDIM / 2; e2++)
        w2p[e2] = pk2(W2[(2 * e2) * CDIM + d], W2[(2 * e2 + 1) * CDIM + d]);
    const float b2d = b2[d];

    const int n0 = blockIdx.x * NODES_PER_BLOCK;
    for (int i = 0; i < NODES_PER_BLOCK; i++) {
        const int nn = n0 + i;
        const float cv = g_C[nn * CDIM + d];

        // neighbor indices: 4 uniform LDG.128 (no 16-reg array held live)
        const int4* jr = (const int4*)&g_knn[nn * KNN];
        int4 j4[4];
#pragma unroll
        for (int v = 0; v < 4; v++) j4[v] = jr[v];
        const int* jv = (const int*)j4;
#pragma unroll
        for (int k = 0; k < KNN; k++)
            gs[k][d] = fmaxf(cv + g_B[jv[k] * CDIM + d], 0.0f);
        __syncthreads();

        float m = -3.4e38f;
#pragma unroll
        for (int k = 0; k < KNN; k++) {
            const ulonglong2* gp = (const ulonglong2*)gs[k];
            unsigned long long a0 = 0ULL, a1 = 0ULL, a2 = 0ULL, a3 = 0ULL;
#pragma unroll
            for (int e8 = 0; e8 < CDIM / 8; e8++) {
                ulonglong2 g0 = gp[2 * e8];         // LDS.128 broadcast
                ulonglong2 g1 = gp[2 * e8 + 1];
                a0 = fma2(g0.x, w2p[4 * e8 + 0], a0);
                a1 = fma2(g0.y, w2p[4 * e8 + 1], a1);
                a2 = fma2(g1.x, w2p[4 * e8 + 2], a2);
                a3 = fma2(g1.y, w2p[4 * e8 + 3], a3);
            }
            a0 = add2(a0, a1);
            a2 = add2(a2, a3);
            a0 = add2(a0, a2);
            float lo, hi;
            upk2(a0, lo, hi);
            m = fmaxf(m, lo + hi);
        }
        out[nn * CDIM + d] = m + b2d;
        __syncthreads();   // gs reused next node
    }
}

// ============================================================
extern "C" void kernel_launch(void* const* d_in, const int* in_sizes, int n_in,
                              void* d_out, int out_size) {
    const float* x   = (const float*)d_in[0];
    const float* pos = (const float*)d_in[1];
    const float* W1  = (const float*)d_in[2];
    const float* b1  = (const float*)d_in[3];
    const float* W2  = (const float*)d_in[4];
    const float* b2  = (const float*)d_in[5];
    float* out = (float*)d_out;

    int n = in_sizes[1] / 3;
    if (n > NMAX) n = NMAX;

    pack_pos_kernel<<<(n / 2 + 255) / 256, 256>>>(pos, n);
    knn_kernel<<<n / (KNN_WARPS * 2), KNN_THREADS>>>(n);
    feat_kernel<<<(n * CDIM + 255) / 256, 256>>>(x, W1, b1, n);
    edge_kernel<<<n / NODES_PER_BLOCK, CDIM>>>(W2, b2, out, n);
}